// round 4
// baseline (speedup 1.0000x reference)
#include <cuda_runtime.h>
#include <cuda_bf16.h>
#include <cstdint>

// Problem dims
#define BB   8
#define SS   4096
#define DD   1024
#define HH   16
#define DHH  64
#define TT   (BB*SS)      // 32768 tokens
#define KK3  (3*DD)       // 3072: [hi|hi|lo] x [bhi|blo|bhi] 3-term split

// ---------------------------------------------------------------------------
// Scratch (static __device__ — no allocations allowed)
// ---------------------------------------------------------------------------
__device__ __nv_bfloat16 g_Xs[(size_t)TT * KK3];          // x split      192 MiB
__device__ __nv_bfloat16 g_Ws[4][(size_t)DD * KK3];       // wq,wk,wv,wo   24 MiB
__device__ float         g_Q [(size_t)TT * DD];           // 128 MiB
__device__ float         g_K [(size_t)TT * DD];           // 128 MiB
__device__ float         g_V [(size_t)TT * DD];           // 128 MiB
__device__ __nv_bfloat16 g_Cs[(size_t)TT * KK3];          // ctx split    192 MiB

// ---------------------------------------------------------------------------
// Split fp32 -> 3-term bf16 rows.
// A-side layout (activations):  [hi | hi | lo]
// B-side layout (weights):      [hi | lo | hi]
// dot(A_row, B_row) = hi*bhi + hi*blo + lo*bhi  (exact minus lo*blo ~2^-16).
// One thread per float4. Grid sized exactly. cols = 1024.
// ---------------------------------------------------------------------------
template <bool ASIDE>
__global__ void split_kernel(const float* __restrict__ src,
                             __nv_bfloat16* __restrict__ dst, int cols) {
    size_t i = (size_t)blockIdx.x * blockDim.x + threadIdx.x;  // float4 idx
    float4 v = ((const float4*)src)[i];
    size_t e = i * 4;
    size_t r = e / cols;
    int    c = (int)(e % cols);
    float f[4] = {v.x, v.y, v.z, v.w};
    __nv_bfloat16 hi[4], lo[4];
#pragma unroll
    for (int j = 0; j < 4; j++) {
        hi[j] = __float2bfloat16(f[j]);
        lo[j] = __float2bfloat16(f[j] - __bfloat162float(hi[j]));
    }
    __nv_bfloat162 hv0 = __halves2bfloat162(hi[0], hi[1]);
    __nv_bfloat162 hv1 = __halves2bfloat162(hi[2], hi[3]);
    __nv_bfloat162 lv0 = __halves2bfloat162(lo[0], lo[1]);
    __nv_bfloat162 lv1 = __halves2bfloat162(lo[2], lo[3]);
    __nv_bfloat16* d0 = dst + r * (size_t)(3 * cols) + c;   // segment 0
    __nv_bfloat16* d1 = d0 + cols;                           // segment 1
    __nv_bfloat16* d2 = d1 + cols;                           // segment 2
    if (ASIDE) {
        // [hi | hi | lo]
        ((__nv_bfloat162*)d0)[0] = hv0; ((__nv_bfloat162*)d0)[1] = hv1;
        ((__nv_bfloat162*)d1)[0] = hv0; ((__nv_bfloat162*)d1)[1] = hv1;
        ((__nv_bfloat162*)d2)[0] = lv0; ((__nv_bfloat162*)d2)[1] = lv1;
    } else {
        // [hi | lo | hi]
        ((__nv_bfloat162*)d0)[0] = hv0; ((__nv_bfloat162*)d0)[1] = hv1;
        ((__nv_bfloat162*)d1)[0] = lv0; ((__nv_bfloat162*)d1)[1] = lv1;
        ((__nv_bfloat162*)d2)[0] = hv0; ((__nv_bfloat162*)d2)[1] = hv1;
    }
}

// ---------------------------------------------------------------------------
// bf16 NT GEMM:  C[M,N] = A[M,K3] * B[N,K3]^T + bias,  fp32 accumulate.
// M = 32768 (tokens), N = 1024, K3 = 3072.
// Block tile 128x128, warp tile 64x32, kTile 32, double-buffered smem,
// stride-40 bf16 padding (conflict-free fragment loads).
// blockIdx.z selects (B, bias, C) triple so QKV runs as one launch.
// ---------------------------------------------------------------------------
struct GemmArgs {
    const __nv_bfloat16* A;
    const __nv_bfloat16* Bm[3];
    const float*         bias[3];
    float*               C[3];
};

#define BM 128
#define BN 128
#define BK 32
#define SST 40   // smem row stride in bf16

__device__ __forceinline__ void mma16816(float c[4], uint32_t a0, uint32_t a1,
                                         uint32_t a2, uint32_t a3,
                                         uint32_t b0, uint32_t b1) {
    asm volatile(
        "mma.sync.aligned.m16n8k16.row.col.f32.bf16.bf16.f32 "
        "{%0,%1,%2,%3}, {%4,%5,%6,%7}, {%8,%9}, {%0,%1,%2,%3};\n"
        : "+f"(c[0]), "+f"(c[1]), "+f"(c[2]), "+f"(c[3])
        : "r"(a0), "r"(a1), "r"(a2), "r"(a3), "r"(b0), "r"(b1));
}

__global__ void __launch_bounds__(256) gemm_kernel(GemmArgs args) {
    __shared__ __nv_bfloat16 As[2][BM][SST];
    __shared__ __nv_bfloat16 Bs[2][BN][SST];

    const int z = blockIdx.z;
    const __nv_bfloat16* __restrict__ A  = args.A;
    const __nv_bfloat16* __restrict__ Bw = args.Bm[z];
    const float* __restrict__ bias       = args.bias[z];
    float* __restrict__ C                = args.C[z];

    const int bm  = blockIdx.y * BM;
    const int bn  = blockIdx.x * BN;
    const int tid = threadIdx.x;
    const int warp = tid >> 5, lane = tid & 31;
    const int wm = (warp >> 2) * 64;   // 0/64
    const int wn = (warp & 3) * 32;    // 0/32/64/96
    const int qr = lane >> 2, qc = lane & 3;

    float acc[4][4][4];
#pragma unroll
    for (int i = 0; i < 4; i++)
#pragma unroll
        for (int j = 0; j < 4; j++)
#pragma unroll
            for (int r = 0; r < 4; r++) acc[i][j][r] = 0.f;

    // loader: 512 x 16B chunks per matrix per stage; 2 per thread per matrix
    const int e0 = tid, e1 = tid + 256;
    const int ra0_row = e0 >> 2, ra0_c8 = (e0 & 3) * 8;
    const int ra1_row = e1 >> 2, ra1_c8 = (e1 & 3) * 8;

    auto gload = [&](const __nv_bfloat16* base, int row, int c8, int kt) {
        return *(const int4*)(base + (size_t)row * KK3 + kt * BK + c8);
    };
    auto sstore = [&](__nv_bfloat16 (*sm)[SST], int row, int c8, int4 v) {
        *(uint2*)&sm[row][c8]     = make_uint2((unsigned)v.x, (unsigned)v.y);
        *(uint2*)&sm[row][c8 + 4] = make_uint2((unsigned)v.z, (unsigned)v.w);
    };

    // prefetch stage 0
    int4 pa0 = gload(A,  bm + ra0_row, ra0_c8, 0);
    int4 pa1 = gload(A,  bm + ra1_row, ra1_c8, 0);
    int4 pb0 = gload(Bw, bn + ra0_row, ra0_c8, 0);
    int4 pb1 = gload(Bw, bn + ra1_row, ra1_c8, 0);
    sstore(As[0], ra0_row, ra0_c8, pa0);
    sstore(As[0], ra1_row, ra1_c8, pa1);
    sstore(Bs[0], ra0_row, ra0_c8, pb0);
    sstore(Bs[0], ra1_row, ra1_c8, pb1);
    __syncthreads();

    const int NKT = KK3 / BK;   // 96
    for (int kt = 0; kt < NKT; kt++) {
        const int s = kt & 1;
        if (kt + 1 < NKT) {
            pa0 = gload(A,  bm + ra0_row, ra0_c8, kt + 1);
            pa1 = gload(A,  bm + ra1_row, ra1_c8, kt + 1);
            pb0 = gload(Bw, bn + ra0_row, ra0_c8, kt + 1);
            pb1 = gload(Bw, bn + ra1_row, ra1_c8, kt + 1);
        }
#pragma unroll
        for (int kk = 0; kk < 2; kk++) {
            const int k0 = kk * 16;
            uint32_t bf[4][2];
#pragma unroll
            for (int j = 0; j < 4; j++) {
                bf[j][0] = *(const uint32_t*)&Bs[s][wn + j * 8 + qr][k0 + qc * 2];
                bf[j][1] = *(const uint32_t*)&Bs[s][wn + j * 8 + qr][k0 + qc * 2 + 8];
            }
#pragma unroll
            for (int i = 0; i < 4; i++) {
                uint32_t a0 = *(const uint32_t*)&As[s][wm + i * 16 + qr][k0 + qc * 2];
                uint32_t a1 = *(const uint32_t*)&As[s][wm + i * 16 + qr + 8][k0 + qc * 2];
                uint32_t a2 = *(const uint32_t*)&As[s][wm + i * 16 + qr][k0 + qc * 2 + 8];
                uint32_t a3 = *(const uint32_t*)&As[s][wm + i * 16 + qr + 8][k0 + qc * 2 + 8];
#pragma unroll
                for (int j = 0; j < 4; j++)
                    mma16816(acc[i][j], a0, a1, a2, a3, bf[j][0], bf[j][1]);
            }
        }
        if (kt + 1 < NKT) {
            const int sn = s ^ 1;
            sstore(As[sn], ra0_row, ra0_c8, pa0);
            sstore(As[sn], ra1_row, ra1_c8, pa1);
            sstore(Bs[sn], ra0_row, ra0_c8, pb0);
            sstore(Bs[sn], ra1_row, ra1_c8, pb1);
        }
        __syncthreads();
    }

    // epilogue: fp32 stores + bias
#pragma unroll
    for (int i = 0; i < 4; i++) {
#pragma unroll
        for (int j = 0; j < 4; j++) {
            const int row = bm + wm + i * 16 + qr;
            const int col = bn + wn + j * 8 + qc * 2;
            const float b0 = bias[col], b1 = bias[col + 1];
            float2 v0 = make_float2(acc[i][j][0] + b0, acc[i][j][1] + b1);
            float2 v1 = make_float2(acc[i][j][2] + b0, acc[i][j][3] + b1);
            *(float2*)&C[(size_t)row * DD + col]       = v0;
            *(float2*)&C[(size_t)(row + 8) * DD + col] = v1;
        }
    }
}

// ---------------------------------------------------------------------------
// Per-token attention over the HEAD axis: scores[h][g] = q_h . k_g / 8,
// softmax over g, ctx[h][d] = sum_g p[h][g] v[g][d].
// One warp per token, 2 tokens per block. Emits ctx already split to
// A-side 3-term layout [hi | hi | lo].
// ---------------------------------------------------------------------------
__global__ void __launch_bounds__(64) attn_kernel(
    const float* __restrict__ Q, const float* __restrict__ K,
    const float* __restrict__ V, __nv_bfloat16* __restrict__ Cs) {
    __shared__ float sQ[2][DD], sK[2][DD], sV[2][DD];
    __shared__ float sS[2][HH][HH];

    const int warp = threadIdx.x >> 5, lane = threadIdx.x & 31;
    const size_t t = (size_t)blockIdx.x * 2 + warp;

    const float4* q4 = (const float4*)(Q + t * DD);
    const float4* k4 = (const float4*)(K + t * DD);
    const float4* v4 = (const float4*)(V + t * DD);
#pragma unroll
    for (int i = lane; i < DD / 4; i += 32) {
        ((float4*)sQ[warp])[i] = q4[i];
        ((float4*)sK[warp])[i] = k4[i];
        ((float4*)sV[warp])[i] = v4[i];
    }
    __syncwarp();

    // scores
    for (int p = lane; p < HH * HH; p += 32) {
        const int h = p >> 4, g = p & 15;
        const float* q = &sQ[warp][h * DHH];
        const float* k = &sK[warp][g * DHH];
        float s = 0.f;
#pragma unroll
        for (int d = 0; d < DHH; d++) s += q[d] * k[d];
        sS[warp][h][g] = s * 0.125f;   // 1/sqrt(64)
    }
    __syncwarp();

    // softmax over g, one lane per head row
    if (lane < HH) {
        float mx = -1e30f;
#pragma unroll
        for (int g = 0; g < HH; g++) mx = fmaxf(mx, sS[warp][lane][g]);
        float sum = 0.f;
#pragma unroll
        for (int g = 0; g < HH; g++) {
            float e = expf(sS[warp][lane][g] - mx);
            sS[warp][lane][g] = e;
            sum += e;
        }
        const float inv = 1.f / sum;
#pragma unroll
        for (int g = 0; g < HH; g++) sS[warp][lane][g] *= inv;
    }
    __syncwarp();

    // ctx + 3-term split store [hi | hi | lo]
    __nv_bfloat16* out = Cs + t * KK3;
    for (int o = lane; o < DD; o += 32) {
        const int h = o >> 6, d = o & 63;
        float c = 0.f;
#pragma unroll
        for (int g = 0; g < HH; g++) c += sS[warp][h][g] * sV[warp][g * DHH + d];
        __nv_bfloat16 hi = __float2bfloat16(c);
        __nv_bfloat16 lo = __float2bfloat16(c - __bfloat162float(hi));
        out[o]          = hi;
        out[DD + o]     = hi;
        out[2 * DD + o] = lo;
    }
}

// ---------------------------------------------------------------------------
// Launch
// ---------------------------------------------------------------------------
extern "C" void kernel_launch(void* const* d_in, const int* in_sizes, int n_in,
                              void* d_out, int out_size) {
    (void)in_sizes; (void)n_in; (void)out_size;
    const float* x  = (const float*)d_in[0];
    const float* wq = (const float*)d_in[1];
    const float* bq = (const float*)d_in[2];
    const float* wk = (const float*)d_in[3];
    const float* bk = (const float*)d_in[4];
    const float* wv = (const float*)d_in[5];
    const float* bv = (const float*)d_in[6];
    const float* wo = (const float*)d_in[7];
    const float* bo = (const float*)d_in[8];
    float* out = (float*)d_out;

    __nv_bfloat16 *Xs, *Ws, *Cs;
    float *Q, *K, *V;
    cudaGetSymbolAddress((void**)&Xs, g_Xs);
    cudaGetSymbolAddress((void**)&Ws, g_Ws);
    cudaGetSymbolAddress((void**)&Cs, g_Cs);
    cudaGetSymbolAddress((void**)&Q,  g_Q);
    cudaGetSymbolAddress((void**)&K,  g_K);
    cudaGetSymbolAddress((void**)&V,  g_V);
    const size_t WSTRIDE = (size_t)DD * KK3;

    // 1) split inputs: x -> A-layout, weights -> B-layout
    split_kernel<true ><<<(size_t)TT * DD / 4 / 256, 256>>>(x, Xs, DD);
    split_kernel<false><<<(size_t)DD * DD / 4 / 256, 256>>>(wq, Ws + 0 * WSTRIDE, DD);
    split_kernel<false><<<(size_t)DD * DD / 4 / 256, 256>>>(wk, Ws + 1 * WSTRIDE, DD);
    split_kernel<false><<<(size_t)DD * DD / 4 / 256, 256>>>(wv, Ws + 2 * WSTRIDE, DD);
    split_kernel<false><<<(size_t)DD * DD / 4 / 256, 256>>>(wo, Ws + 3 * WSTRIDE, DD);

    // 2) fused QKV GEMMs (z = q/k/v)
    GemmArgs ga;
    ga.A = Xs;
    ga.Bm[0] = Ws + 0 * WSTRIDE; ga.Bm[1] = Ws + 1 * WSTRIDE; ga.Bm[2] = Ws + 2 * WSTRIDE;
    ga.bias[0] = bq; ga.bias[1] = bk; ga.bias[2] = bv;
    ga.C[0] = Q; ga.C[1] = K; ga.C[2] = V;
    gemm_kernel<<<dim3(DD / BN, TT / BM, 3), 256>>>(ga);

    // 3) per-token head-axis attention -> ctx (3-term split bf16)
    attn_kernel<<<TT / 2, 64>>>(Q, K, V, Cs);

    // 4) output projection
    GemmArgs go;
    go.A = Cs;
    go.Bm[0] = Ws + 3 * WSTRIDE; go.Bm[1] = go.Bm[0]; go.Bm[2] = go.Bm[0];
    go.bias[0] = bo; go.bias[1] = bo; go.bias[2] = bo;
    go.C[0] = out; go.C[1] = out; go.C[2] = out;
    gemm_kernel<<<dim3(DD / BN, TT / BM, 1), 256>>>(go);
}

// round 5
// speedup vs baseline: 1.2301x; 1.2301x over previous
#include <cuda_runtime.h>
#include <cuda_bf16.h>
#include <cstdint>

// Problem dims
#define BB   8
#define SS   4096
#define DD   1024
#define HH   16
#define DHH  64
#define TT   (BB*SS)      // 32768 tokens
#define KK2  (2*DD)       // 2048: operands stored [hi|lo]; 3 virtual K-segments in GEMM

// ---------------------------------------------------------------------------
// Scratch (static __device__ — no allocations allowed)
// ---------------------------------------------------------------------------
__device__ __nv_bfloat16 g_Xs[(size_t)TT * KK2];          // x split      128 MiB
__device__ __nv_bfloat16 g_Ws[4][(size_t)DD * KK2];       // weights       16 MiB
__device__ float         g_Q [(size_t)TT * DD];           // 128 MiB
__device__ float         g_K [(size_t)TT * DD];           // 128 MiB
__device__ float         g_V [(size_t)TT * DD];           // 128 MiB
__device__ __nv_bfloat16 g_Cs[(size_t)TT * KK2];          // ctx split    128 MiB

// ---------------------------------------------------------------------------
// Split fp32 -> [hi | lo] bf16 rows. dst row stride = 2*cols.
// GEMM computes hi*bhi + hi*blo + lo*bhi via segment indexing (exact minus
// lo*blo ~ 2^-16 relative).
// ---------------------------------------------------------------------------
__global__ void split_kernel(const float* __restrict__ src,
                             __nv_bfloat16* __restrict__ dst, int cols) {
    size_t i = (size_t)blockIdx.x * blockDim.x + threadIdx.x;  // float4 idx
    float4 v = ((const float4*)src)[i];
    size_t e = i * 4;
    size_t r = e / cols;
    int    c = (int)(e % cols);
    float f[4] = {v.x, v.y, v.z, v.w};
    __nv_bfloat16 hi[4], lo[4];
#pragma unroll
    for (int j = 0; j < 4; j++) {
        hi[j] = __float2bfloat16(f[j]);
        lo[j] = __float2bfloat16(f[j] - __bfloat162float(hi[j]));
    }
    __nv_bfloat16* dhi = dst + r * (size_t)(2 * cols) + c;
    __nv_bfloat16* dlo = dhi + cols;
    ((__nv_bfloat162*)dhi)[0] = __halves2bfloat162(hi[0], hi[1]);
    ((__nv_bfloat162*)dhi)[1] = __halves2bfloat162(hi[2], hi[3]);
    ((__nv_bfloat162*)dlo)[0] = __halves2bfloat162(lo[0], lo[1]);
    ((__nv_bfloat162*)dlo)[1] = __halves2bfloat162(lo[2], lo[3]);
}

// ---------------------------------------------------------------------------
// bf16 NT GEMM with 3-segment K traversal:
//   C[M,N] = sum over segments { A[:,hi]*B[:,hi]^T + A[:,hi]*B[:,lo]^T
//                              + A[:,lo]*B[:,hi]^T } + bias
// Block 128x128, warp 64x32, BK=32, 4-stage cp.async pipeline, ldmatrix
// fragment loads, stride-40 smem padding (conflict-free for LDSM).
// ---------------------------------------------------------------------------
struct GemmArgs {
    const __nv_bfloat16* A;
    const __nv_bfloat16* Bm[3];
    const float*         bias[3];
    float*               C[3];
};

#define BM 128
#define BN 128
#define BK 32
#define SST 40      // smem row stride (bf16)
#define STAGES 4
#define NKT 96      // 3 segments x 32 k-tiles
#define SMEM_BYTES (STAGES * (BM + BN) * SST * 2)   // 81920

__device__ __forceinline__ void mma16816(float c[4], uint32_t a0, uint32_t a1,
                                         uint32_t a2, uint32_t a3,
                                         uint32_t b0, uint32_t b1) {
    asm volatile(
        "mma.sync.aligned.m16n8k16.row.col.f32.bf16.bf16.f32 "
        "{%0,%1,%2,%3}, {%4,%5,%6,%7}, {%8,%9}, {%0,%1,%2,%3};\n"
        : "+f"(c[0]), "+f"(c[1]), "+f"(c[2]), "+f"(c[3])
        : "r"(a0), "r"(a1), "r"(a2), "r"(a3), "r"(b0), "r"(b1));
}

__device__ __forceinline__ void ldsm4(uint32_t& r0, uint32_t& r1,
                                      uint32_t& r2, uint32_t& r3, uint32_t a) {
    asm volatile("ldmatrix.sync.aligned.m8n8.x4.shared.b16 {%0,%1,%2,%3}, [%4];"
                 : "=r"(r0), "=r"(r1), "=r"(r2), "=r"(r3) : "r"(a));
}

__device__ __forceinline__ void cp16(uint32_t s, const void* g) {
    asm volatile("cp.async.cg.shared.global [%0], [%1], 16;" :: "r"(s), "l"(g));
}

__global__ void __launch_bounds__(256, 2) gemm_kernel(GemmArgs args) {
    extern __shared__ __nv_bfloat16 smem[];

    const int z = blockIdx.z;
    const __nv_bfloat16* __restrict__ A  = args.A;
    const __nv_bfloat16* __restrict__ Bw = args.Bm[z];
    const float* __restrict__ bias       = args.bias[z];
    float* __restrict__ C                = args.C[z];

    const int bm  = blockIdx.y * BM;
    const int bn  = blockIdx.x * BN;
    const int tid = threadIdx.x;
    const int warp = tid >> 5, lane = tid & 31;
    const int wm = (warp >> 2) * 64;   // 0/64
    const int wn = (warp & 3) * 32;    // 0/32/64/96

    const uint32_t sbase = (uint32_t)__cvta_generic_to_shared(smem);
    auto sA = [&](int s, int r, int c) -> uint32_t {
        return sbase + (uint32_t)(((s * BM + r) * SST + c) * 2);
    };
    auto sB = [&](int s, int r, int c) -> uint32_t {
        return sbase + (uint32_t)(((STAGES * BM + s * BN + r) * SST + c) * 2);
    };

    // ldmatrix lane address components
    const int alr = lane & 15, alc = (lane >> 4) * 8;                // A x4
    const int blr = ((lane >> 4) & 1) * 8 + (lane & 7);              // B x4
    const int blc = ((lane >> 3) & 1) * 8;

    // cp.async loader mapping: 4 x 16B per thread per stage per matrix-half
    const int r0row = tid >> 2, r1row = 64 + (tid >> 2);
    const int cc8   = (tid & 3) * 8;

    auto issue = [&](int kt, int s) {
        const int p  = kt >> 5, u = kt & 31;
        const int ac = (p == 2 ? DD : 0) + u * BK;
        const int bc = (p == 1 ? DD : 0) + u * BK;
        cp16(sA(s, r0row, cc8), A  + (size_t)(bm + r0row) * KK2 + ac + cc8);
        cp16(sA(s, r1row, cc8), A  + (size_t)(bm + r1row) * KK2 + ac + cc8);
        cp16(sB(s, r0row, cc8), Bw + (size_t)(bn + r0row) * KK2 + bc + cc8);
        cp16(sB(s, r1row, cc8), Bw + (size_t)(bn + r1row) * KK2 + bc + cc8);
    };

    float acc[4][4][4];
#pragma unroll
    for (int i = 0; i < 4; i++)
#pragma unroll
        for (int j = 0; j < 4; j++)
#pragma unroll
            for (int r = 0; r < 4; r++) acc[i][j][r] = 0.f;

    // prologue: fill STAGES-1 stages
#pragma unroll
    for (int p = 0; p < STAGES - 1; p++) {
        issue(p, p);
        asm volatile("cp.async.commit_group;");
    }

    for (int kt = 0; kt < NKT; kt++) {
        asm volatile("cp.async.wait_group %0;" :: "n"(STAGES - 2));
        __syncthreads();
        if (kt + STAGES - 1 < NKT) issue(kt + STAGES - 1, (kt + STAGES - 1) & (STAGES - 1));
        asm volatile("cp.async.commit_group;");

        const int s = kt & (STAGES - 1);
#pragma unroll
        for (int kk = 0; kk < 2; kk++) {
            const int k0 = kk * 16;
            uint32_t a[4][4], b[4][2];
#pragma unroll
            for (int i = 0; i < 4; i++)
                ldsm4(a[i][0], a[i][1], a[i][2], a[i][3],
                      sA(s, wm + i * 16 + alr, k0 + alc));
#pragma unroll
            for (int jp = 0; jp < 2; jp++)
                ldsm4(b[2 * jp][0], b[2 * jp][1], b[2 * jp + 1][0], b[2 * jp + 1][1],
                      sB(s, wn + jp * 16 + blr, k0 + blc));
#pragma unroll
            for (int i = 0; i < 4; i++)
#pragma unroll
                for (int j = 0; j < 4; j++)
                    mma16816(acc[i][j], a[i][0], a[i][1], a[i][2], a[i][3],
                             b[j][0], b[j][1]);
        }
    }

    // epilogue: fp32 stores + bias
    const int qr = lane >> 2, qc = lane & 3;
#pragma unroll
    for (int i = 0; i < 4; i++) {
#pragma unroll
        for (int j = 0; j < 4; j++) {
            const int row = bm + wm + i * 16 + qr;
            const int col = bn + wn + j * 8 + qc * 2;
            const float b0 = bias[col], b1 = bias[col + 1];
            float2 v0 = make_float2(acc[i][j][0] + b0, acc[i][j][1] + b1);
            float2 v1 = make_float2(acc[i][j][2] + b0, acc[i][j][3] + b1);
            *(float2*)&C[(size_t)row * DD + col]       = v0;
            *(float2*)&C[(size_t)(row + 8) * DD + col] = v1;
        }
    }
}

// ---------------------------------------------------------------------------
// Per-token attention over the HEAD axis. One warp per token. Emits ctx
// split to [hi | lo] (row stride KK2).
// ---------------------------------------------------------------------------
__global__ void __launch_bounds__(64) attn_kernel(
    const float* __restrict__ Q, const float* __restrict__ K,
    const float* __restrict__ V, __nv_bfloat16* __restrict__ Cs) {
    __shared__ float sQ[2][DD], sK[2][DD], sV[2][DD];
    __shared__ float sS[2][HH][HH];

    const int warp = threadIdx.x >> 5, lane = threadIdx.x & 31;
    const size_t t = (size_t)blockIdx.x * 2 + warp;

    const float4* q4 = (const float4*)(Q + t * DD);
    const float4* k4 = (const float4*)(K + t * DD);
    const float4* v4 = (const float4*)(V + t * DD);
#pragma unroll
    for (int i = lane; i < DD / 4; i += 32) {
        ((float4*)sQ[warp])[i] = q4[i];
        ((float4*)sK[warp])[i] = k4[i];
        ((float4*)sV[warp])[i] = v4[i];
    }
    __syncwarp();

    for (int p = lane; p < HH * HH; p += 32) {
        const int h = p >> 4, g = p & 15;
        const float* q = &sQ[warp][h * DHH];
        const float* k = &sK[warp][g * DHH];
        float s = 0.f;
#pragma unroll
        for (int d = 0; d < DHH; d++) s += q[d] * k[d];
        sS[warp][h][g] = s * 0.125f;   // 1/sqrt(64)
    }
    __syncwarp();

    if (lane < HH) {
        float mx = -1e30f;
#pragma unroll
        for (int g = 0; g < HH; g++) mx = fmaxf(mx, sS[warp][lane][g]);
        float sum = 0.f;
#pragma unroll
        for (int g = 0; g < HH; g++) {
            float e = expf(sS[warp][lane][g] - mx);
            sS[warp][lane][g] = e;
            sum += e;
        }
        const float inv = 1.f / sum;
#pragma unroll
        for (int g = 0; g < HH; g++) sS[warp][lane][g] *= inv;
    }
    __syncwarp();

    __nv_bfloat16* out = Cs + t * KK2;
    for (int o = lane; o < DD; o += 32) {
        const int h = o >> 6, d = o & 63;
        float c = 0.f;
#pragma unroll
        for (int g = 0; g < HH; g++) c += sS[warp][h][g] * sV[warp][g * DHH + d];
        __nv_bfloat16 hi = __float2bfloat16(c);
        __nv_bfloat16 lo = __float2bfloat16(c - __bfloat162float(hi));
        out[o]      = hi;
        out[DD + o] = lo;
    }
}

// ---------------------------------------------------------------------------
// Launch
// ---------------------------------------------------------------------------
extern "C" void kernel_launch(void* const* d_in, const int* in_sizes, int n_in,
                              void* d_out, int out_size) {
    (void)in_sizes; (void)n_in; (void)out_size;
    const float* x  = (const float*)d_in[0];
    const float* wq = (const float*)d_in[1];
    const float* bq = (const float*)d_in[2];
    const float* wk = (const float*)d_in[3];
    const float* bk = (const float*)d_in[4];
    const float* wv = (const float*)d_in[5];
    const float* bv = (const float*)d_in[6];
    const float* wo = (const float*)d_in[7];
    const float* bo = (const float*)d_in[8];
    float* out = (float*)d_out;

    __nv_bfloat16 *Xs, *Ws, *Cs;
    float *Q, *K, *V;
    cudaGetSymbolAddress((void**)&Xs, g_Xs);
    cudaGetSymbolAddress((void**)&Ws, g_Ws);
    cudaGetSymbolAddress((void**)&Cs, g_Cs);
    cudaGetSymbolAddress((void**)&Q,  g_Q);
    cudaGetSymbolAddress((void**)&K,  g_K);
    cudaGetSymbolAddress((void**)&V,  g_V);
    const size_t WSTRIDE = (size_t)DD * KK2;

    cudaFuncSetAttribute(gemm_kernel,
                         cudaFuncAttributeMaxDynamicSharedMemorySize, SMEM_BYTES);

    // 1) split inputs to [hi|lo]
    split_kernel<<<(size_t)TT * DD / 4 / 256, 256>>>(x, Xs, DD);
    split_kernel<<<(size_t)DD * DD / 4 / 256, 256>>>(wq, Ws + 0 * WSTRIDE, DD);
    split_kernel<<<(size_t)DD * DD / 4 / 256, 256>>>(wk, Ws + 1 * WSTRIDE, DD);
    split_kernel<<<(size_t)DD * DD / 4 / 256, 256>>>(wv, Ws + 2 * WSTRIDE, DD);
    split_kernel<<<(size_t)DD * DD / 4 / 256, 256>>>(wo, Ws + 3 * WSTRIDE, DD);

    // 2) fused QKV GEMMs (z = q/k/v)
    GemmArgs ga;
    ga.A = Xs;
    ga.Bm[0] = Ws + 0 * WSTRIDE; ga.Bm[1] = Ws + 1 * WSTRIDE; ga.Bm[2] = Ws + 2 * WSTRIDE;
    ga.bias[0] = bq; ga.bias[1] = bk; ga.bias[2] = bv;
    ga.C[0] = Q; ga.C[1] = K; ga.C[2] = V;
    gemm_kernel<<<dim3(DD / BN, TT / BM, 3), 256, SMEM_BYTES>>>(ga);

    // 3) per-token head-axis attention -> ctx ([hi|lo])
    attn_kernel<<<TT / 2, 64>>>(Q, K, V, Cs);

    // 4) output projection
    GemmArgs go;
    go.A = Cs;
    go.Bm[0] = Ws + 3 * WSTRIDE; go.Bm[1] = go.Bm[0]; go.Bm[2] = go.Bm[0];
    go.bias[0] = bo; go.bias[1] = bo; go.bias[2] = bo;
    go.C[0] = out; go.C[1] = out; go.C[2] = out;
    gemm_kernel<<<dim3(DD / BN, TT / BM, 1), 256, SMEM_BYTES>>>(go);
}

// round 7
// speedup vs baseline: 1.3136x; 1.0679x over previous
#include <cuda_runtime.h>
#include <cuda_bf16.h>
#include <cstdint>

// Problem dims
#define BB   8
#define SS   4096
#define DD   1024
#define HH   16
#define DHH  64
#define TT   (BB*SS)      // 32768 tokens
#define KK2  (2*DD)       // 2048: operands stored [hi|lo]

// ---------------------------------------------------------------------------
// Scratch (static __device__ — no allocations allowed)
// ---------------------------------------------------------------------------
__device__ __nv_bfloat16 g_Xs[(size_t)TT * KK2];          // x split      128 MiB
__device__ __nv_bfloat16 g_Ws[4][(size_t)DD * KK2];       // weights       16 MiB
__device__ float         g_Q [(size_t)TT * DD];
__device__ float         g_K [(size_t)TT * DD];
__device__ float         g_V [(size_t)TT * DD];
__device__ __nv_bfloat16 g_Cs[(size_t)TT * KK2];          // ctx split    128 MiB

// ---------------------------------------------------------------------------
// Split fp32 -> [hi | lo] bf16 rows. GEMM computes hi*bhi + hi*blo + lo*bhi
// (exact minus lo*blo ~ 2^-16 relative).
// ---------------------------------------------------------------------------
__global__ void split_kernel(const float* __restrict__ src,
                             __nv_bfloat16* __restrict__ dst, int cols) {
    size_t i = (size_t)blockIdx.x * blockDim.x + threadIdx.x;  // float4 idx
    float4 v = ((const float4*)src)[i];
    size_t e = i * 4;
    size_t r = e / cols;
    int    c = (int)(e % cols);
    float f[4] = {v.x, v.y, v.z, v.w};
    __nv_bfloat16 hi[4], lo[4];
#pragma unroll
    for (int j = 0; j < 4; j++) {
        hi[j] = __float2bfloat16(f[j]);
        lo[j] = __float2bfloat16(f[j] - __bfloat162float(hi[j]));
    }
    __nv_bfloat16* dhi = dst + r * (size_t)(2 * cols) + c;
    __nv_bfloat16* dlo = dhi + cols;
    ((__nv_bfloat162*)dhi)[0] = __halves2bfloat162(hi[0], hi[1]);
    ((__nv_bfloat162*)dhi)[1] = __halves2bfloat162(hi[2], hi[3]);
    ((__nv_bfloat162*)dlo)[0] = __halves2bfloat162(lo[0], lo[1]);
    ((__nv_bfloat162*)dlo)[1] = __halves2bfloat162(lo[2], lo[3]);
}

// ---------------------------------------------------------------------------
// bf16 NT GEMM, product form:
//   C = Ahi*Bhi^T + Ahi*Blo^T + Alo*Bhi^T + bias   (fp32 accumulate)
// Per k-chunk (BK=32) load Ahi/Alo/Bhi/Blo tiles once, run 3 register-level
// product passes. CTA tile 256x128 (8 warps, warp tile 64x64), 3-stage
// cp.async pipeline, ldmatrix feeds, stride-40 smem padding.
// ---------------------------------------------------------------------------
struct GemmArgs {
    const __nv_bfloat16* A;
    const __nv_bfloat16* Bm[3];
    const float*         bias[3];
    float*               C[3];
};

#define BM 256
#define BN 128
#define BK 32
#define SST 40                       // smem row stride (bf16)
#define STAGES 3
#define NKT 32                       // K=1024 / BK
#define STG_ROWS 768                 // Ahi 256 | Alo 256 | Bhi 128 | Blo 128
#define R_ALO 256
#define R_BHI 512
#define R_BLO 640
#define STAGE_B (STG_ROWS * SST * 2)             // 61440
#define SMEM_BYTES (STAGES * STAGE_B)            // 184320

__device__ __forceinline__ void mma16816(float c[4], uint32_t a0, uint32_t a1,
                                         uint32_t a2, uint32_t a3,
                                         uint32_t b0, uint32_t b1) {
    asm volatile(
        "mma.sync.aligned.m16n8k16.row.col.f32.bf16.bf16.f32 "
        "{%0,%1,%2,%3}, {%4,%5,%6,%7}, {%8,%9}, {%0,%1,%2,%3};\n"
        : "+f"(c[0]), "+f"(c[1]), "+f"(c[2]), "+f"(c[3])
        : "r"(a0), "r"(a1), "r"(a2), "r"(a3), "r"(b0), "r"(b1));
}

__device__ __forceinline__ void ldsm4(uint32_t& r0, uint32_t& r1,
                                      uint32_t& r2, uint32_t& r3, uint32_t a) {
    asm volatile("ldmatrix.sync.aligned.m8n8.x4.shared.b16 {%0,%1,%2,%3}, [%4];"
                 : "=r"(r0), "=r"(r1), "=r"(r2), "=r"(r3) : "r"(a));
}

__device__ __forceinline__ void cp16(uint32_t s, const void* g) {
    asm volatile("cp.async.cg.shared.global [%0], [%1], 16;" :: "r"(s), "l"(g));
}

__global__ void __launch_bounds__(256, 1) gemm_kernel(GemmArgs args) {
    extern __shared__ __nv_bfloat16 smem[];

    const int z = blockIdx.z;
    const __nv_bfloat16* __restrict__ A  = args.A;
    const __nv_bfloat16* __restrict__ Bw = args.Bm[z];
    const float* __restrict__ bias       = args.bias[z];
    float* __restrict__ C                = args.C[z];

    const int bn  = blockIdx.x * BN;
    const int bm  = blockIdx.y * BM;
    const int tid = threadIdx.x;
    const int warp = tid >> 5, lane = tid & 31;
    const int wm = (warp >> 1) * 64;   // 0/64/128/192
    const int wn = (warp & 1) * 64;    // 0/64

    const uint32_t sbase = (uint32_t)__cvta_generic_to_shared(smem);
    auto srow = [&](int s, int r, int c) -> uint32_t {
        return sbase + (uint32_t)(((s * STG_ROWS + r) * SST + c) * 2);
    };

    // ldmatrix lane address components
    const int alr = lane & 15, alc = (lane >> 4) * 8;     // x4 (16 rows)
    const int blr = ((lane >> 4) & 1) * 8 + (lane & 7);
    const int blc = ((lane >> 3) & 1) * 8;

    auto issue = [&](int kt, int s) {
        const int kc = kt * BK;
#pragma unroll
        for (int j = 0; j < 12; j++) {
            const int c   = tid + 256 * j;        // 0..3071 16B-chunks
            const int row = c >> 2;               // 4 chunks per 32-col row
            const int c8  = (c & 3) * 8;
            const __nv_bfloat16* g;
            if (row < R_ALO)                                       // Ahi
                g = A  + (size_t)(bm + row) * KK2 + kc + c8;
            else if (row < R_BHI)                                  // Alo
                g = A  + (size_t)(bm + row - R_ALO) * KK2 + DD + kc + c8;
            else if (row < R_BLO)                                  // Bhi
                g = Bw + (size_t)(bn + row - R_BHI) * KK2 + kc + c8;
            else                                                   // Blo
                g = Bw + (size_t)(bn + row - R_BLO) * KK2 + DD + kc + c8;
            cp16(srow(s, row, c8), g);
        }
        asm volatile("cp.async.commit_group;");
    };

    float acc[4][8][4];
#pragma unroll
    for (int i = 0; i < 4; i++)
#pragma unroll
        for (int j = 0; j < 8; j++)
#pragma unroll
            for (int r = 0; r < 4; r++) acc[i][j][r] = 0.f;

    issue(0, 0);
    issue(1, 1);

    for (int kt = 0; kt < NKT; kt++) {
        const int s = kt % STAGES;
        if (kt + 2 < NKT) { asm volatile("cp.async.wait_group 1;"); }
        else              { asm volatile("cp.async.wait_group 0;"); }
        __syncthreads();
        if (kt + 2 < NKT) issue(kt + 2, (kt + 2) % STAGES);

#pragma unroll
        for (int kk = 0; kk < 2; kk++) {
            const int k0 = kk * 16;
            uint32_t ahi[4][4], bhi[8][2];
#pragma unroll
            for (int i = 0; i < 4; i++)
                ldsm4(ahi[i][0], ahi[i][1], ahi[i][2], ahi[i][3],
                      srow(s, wm + i * 16 + alr, k0 + alc));
#pragma unroll
            for (int jp = 0; jp < 4; jp++)
                ldsm4(bhi[2 * jp][0], bhi[2 * jp][1],
                      bhi[2 * jp + 1][0], bhi[2 * jp + 1][1],
                      srow(s, R_BHI + wn + jp * 16 + blr, k0 + blc));
            // P1: Ahi * Bhi
#pragma unroll
            for (int i = 0; i < 4; i++)
#pragma unroll
                for (int j = 0; j < 8; j++)
                    mma16816(acc[i][j], ahi[i][0], ahi[i][1], ahi[i][2], ahi[i][3],
                             bhi[j][0], bhi[j][1]);
            // P2: Ahi * Blo
            {
                uint32_t blo[8][2];
#pragma unroll
                for (int jp = 0; jp < 4; jp++)
                    ldsm4(blo[2 * jp][0], blo[2 * jp][1],
                          blo[2 * jp + 1][0], blo[2 * jp + 1][1],
                          srow(s, R_BLO + wn + jp * 16 + blr, k0 + blc));
#pragma unroll
                for (int i = 0; i < 4; i++)
#pragma unroll
                    for (int j = 0; j < 8; j++)
                        mma16816(acc[i][j], ahi[i][0], ahi[i][1], ahi[i][2], ahi[i][3],
                                 blo[j][0], blo[j][1]);
            }
            // P3: Alo * Bhi
            {
                uint32_t alo[4][4];
#pragma unroll
                for (int i = 0; i < 4; i++)
                    ldsm4(alo[i][0], alo[i][1], alo[i][2], alo[i][3],
                          srow(s, R_ALO + wm + i * 16 + alr, k0 + alc));
#pragma unroll
                for (int i = 0; i < 4; i++)
#pragma unroll
                    for (int j = 0; j < 8; j++)
                        mma16816(acc[i][j], alo[i][0], alo[i][1], alo[i][2], alo[i][3],
                                 bhi[j][0], bhi[j][1]);
            }
        }
    }

    // epilogue: fp32 stores + bias
    const int qr = lane >> 2, qc = lane & 3;
#pragma unroll
    for (int i = 0; i < 4; i++) {
#pragma unroll
        for (int j = 0; j < 8; j++) {
            const int row = bm + wm + i * 16 + qr;
            const int col = bn + wn + j * 8 + qc * 2;
            const float b0 = bias[col], b1 = bias[col + 1];
            float2 v0 = make_float2(acc[i][j][0] + b0, acc[i][j][1] + b1);
            float2 v1 = make_float2(acc[i][j][2] + b0, acc[i][j][3] + b1);
            *(float2*)&C[(size_t)row * DD + col]       = v0;
            *(float2*)&C[(size_t)(row + 8) * DD + col] = v1;
        }
    }
}

// ---------------------------------------------------------------------------
// Per-token attention over the HEAD axis. One warp per token. Emits ctx
// split to [hi | lo] (row stride KK2).
// ---------------------------------------------------------------------------
__global__ void __launch_bounds__(64) attn_kernel(
    const float* __restrict__ Q, const float* __restrict__ K,
    const float* __restrict__ V, __nv_bfloat16* __restrict__ Cs) {
    __shared__ float sQ[2][DD], sK[2][DD], sV[2][DD];
    __shared__ float sS[2][HH][HH];

    const int warp = threadIdx.x >> 5, lane = threadIdx.x & 31;
    const size_t t = (size_t)blockIdx.x * 2 + warp;

    const float4* q4 = (const float4*)(Q + t * DD);
    const float4* k4 = (const float4*)(K + t * DD);
    const float4* v4 = (const float4*)(V + t * DD);
#pragma unroll
    for (int i = lane; i < DD / 4; i += 32) {
        ((float4*)sQ[warp])[i] = q4[i];
        ((float4*)sK[warp])[i] = k4[i];
        ((float4*)sV[warp])[i] = v4[i];
    }
    __syncwarp();

    for (int p = lane; p < HH * HH; p += 32) {
        const int h = p >> 4, g = p & 15;
        const float* q = &sQ[warp][h * DHH];
        const float* k = &sK[warp][g * DHH];
        float s = 0.f;
#pragma unroll
        for (int d = 0; d < DHH; d++) s += q[d] * k[d];
        sS[warp][h][g] = s * 0.125f;   // 1/sqrt(64)
    }
    __syncwarp();

    if (lane < HH) {
        float mx = -1e30f;
#pragma unroll
        for (int g = 0; g < HH; g++) mx = fmaxf(mx, sS[warp][lane][g]);
        float sum = 0.f;
#pragma unroll
        for (int g = 0; g < HH; g++) {
            float e = expf(sS[warp][lane][g] - mx);
            sS[warp][lane][g] = e;
            sum += e;
        }
        const float inv = 1.f / sum;
#pragma unroll
        for (int g = 0; g < HH; g++) sS[warp][lane][g] *= inv;
    }
    __syncwarp();

    __nv_bfloat16* out = Cs + t * KK2;
    for (int o = lane; o < DD; o += 32) {
        const int h = o >> 6, d = o & 63;
        float c = 0.f;
#pragma unroll
        for (int g = 0; g < HH; g++) c += sS[warp][h][g] * sV[warp][g * DHH + d];
        __nv_bfloat16 hi = __float2bfloat16(c);
        __nv_bfloat16 lo = __float2bfloat16(c - __bfloat162float(hi));
        out[o]      = hi;
        out[DD + o] = lo;
    }
}

// ---------------------------------------------------------------------------
// Launch
// ---------------------------------------------------------------------------
extern "C" void kernel_launch(void* const* d_in, const int* in_sizes, int n_in,
                              void* d_out, int out_size) {
    (void)in_sizes; (void)n_in; (void)out_size;
    const float* x  = (const float*)d_in[0];
    const float* wq = (const float*)d_in[1];
    const float* bq = (const float*)d_in[2];
    const float* wk = (const float*)d_in[3];
    const float* bk = (const float*)d_in[4];
    const float* wv = (const float*)d_in[5];
    const float* bv = (const float*)d_in[6];
    const float* wo = (const float*)d_in[7];
    const float* bo = (const float*)d_in[8];
    float* out = (float*)d_out;

    __nv_bfloat16 *Xs, *Ws, *Cs;
    float *Q, *K, *V;
    cudaGetSymbolAddress((void**)&Xs, g_Xs);
    cudaGetSymbolAddress((void**)&Ws, g_Ws);
    cudaGetSymbolAddress((void**)&Cs, g_Cs);
    cudaGetSymbolAddress((void**)&Q,  g_Q);
    cudaGetSymbolAddress((void**)&K,  g_K);
    cudaGetSymbolAddress((void**)&V,  g_V);
    const size_t WSTRIDE = (size_t)DD * KK2;

    cudaFuncSetAttribute(gemm_kernel,
                         cudaFuncAttributeMaxDynamicSharedMemorySize, SMEM_BYTES);

    // 1) split inputs to [hi|lo]
    split_kernel<<<(size_t)TT * DD / 4 / 256, 256>>>(x, Xs, DD);
    split_kernel<<<(size_t)DD * DD / 4 / 256, 256>>>(wq, Ws + 0 * WSTRIDE, DD);
    split_kernel<<<(size_t)DD * DD / 4 / 256, 256>>>(wk, Ws + 1 * WSTRIDE, DD);
    split_kernel<<<(size_t)DD * DD / 4 / 256, 256>>>(wv, Ws + 2 * WSTRIDE, DD);
    split_kernel<<<(size_t)DD * DD / 4 / 256, 256>>>(wo, Ws + 3 * WSTRIDE, DD);

    // 2) fused QKV GEMMs (z = q/k/v); x-dim = N-block fastest for A-panel L2 reuse
    GemmArgs ga;
    ga.A = Xs;
    ga.Bm[0] = Ws + 0 * WSTRIDE; ga.Bm[1] = Ws + 1 * WSTRIDE; ga.Bm[2] = Ws + 2 * WSTRIDE;
    ga.bias[0] = bq; ga.bias[1] = bk; ga.bias[2] = bv;
    ga.C[0] = Q; ga.C[1] = K; ga.C[2] = V;
    gemm_kernel<<<dim3(DD / BN, TT / BM, 3), 256, SMEM_BYTES>>>(ga);

    // 3) per-token head-axis attention -> ctx ([hi|lo])
    attn_kernel<<<TT / 2, 64>>>(Q, K, V, Cs);

    // 4) output projection
    GemmArgs go;
    go.A = Cs;
    go.Bm[0] = Ws + 3 * WSTRIDE; go.Bm[1] = go.Bm[0]; go.Bm[2] = go.Bm[0];
    go.bias[0] = bo; go.bias[1] = bo; go.bias[2] = bo;
    go.C[0] = out; go.C[1] = out; go.C[2] = out;
    gemm_kernel<<<dim3(DD / BN, TT / BM, 1), 256, SMEM_BYTES>>>(go);
}